// round 8
// baseline (speedup 1.0000x reference)
#include <cuda_runtime.h>
#include <cuda_bf16.h>
#include <cstddef>

// Problem constants (fixed by the reference setup)
constexpr int B   = 16;
constexpr int TM  = 128;
constexpr int SM_ = 64;
constexpr int SP1 = SM_ + 1;           // 65
constexpr int V   = 1024;
constexpr int NROWS   = B * TM * SP1;  // 133120
constexpr int NGRP    = TM / 8;        // 16 groups of 8 time steps
constexpr int GRP_ROWS = 8 * SP1;      // 520 rows per (batch, group)

// Scratch (device globals: no allocation in kernel_launch). g_cnt starts
// zero-initialized and is reset to zero by the consumer at the end of every
// run, so graph replays are deterministic.
__device__ float g_eb[NROWS];          // exp(blank_lp) per row
__device__ float g_el[NROWS];          // exp(label_lp) per row (0 at s==SM)
__device__ int   g_cnt[B][NGRP];       // produced-row counters

__device__ __forceinline__ int ld_cg(const int* p) {
    int v;
    asm volatile("ld.global.cg.b32 %0, [%1];" : "=r"(v) : "l"(p) : "memory");
    return v;
}

// ---------------------------------------------------------------------------
// Fused kernel.
//  blocks [0, B)      : alpha consumer, one per batch (warp 0 only).
//  blocks [B, ...)    : lse producer, 8 rows per CTA (one warp per row).
// Alpha CTAs are blocks 0..15 so they land in wave 1 and overlap producers.
// ---------------------------------------------------------------------------
__global__ void __launch_bounds__(256)
rnnt_fused_kernel(const float* __restrict__ acts,
                  const int*   __restrict__ labels,
                  const int*   __restrict__ input_lengths,
                  const int*   __restrict__ label_lengths,
                  float*       __restrict__ out)
{
    // =========================== PRODUCER ROLE ===========================
    if (blockIdx.x >= B) {
        const int row  = (blockIdx.x - B) * 8 + (threadIdx.x >> 5);
        const int lane = threadIdx.x & 31;
        if (row >= NROWS) return;

        const float4* p = reinterpret_cast<const float4*>(acts)
                        + (size_t)row * (V / 4);
        float4 v[8];
#pragma unroll
        for (int j = 0; j < 8; j++) v[j] = p[j * 32 + lane];

        float m = v[0].x;
#pragma unroll
        for (int j = 0; j < 8; j++)
            m = fmaxf(m, fmaxf(fmaxf(v[j].x, v[j].y), fmaxf(v[j].z, v[j].w)));
        float s = 0.f;
#pragma unroll
        for (int j = 0; j < 8; j++)
            s += __expf(v[j].x - m) + __expf(v[j].y - m)
               + __expf(v[j].z - m) + __expf(v[j].w - m);
#pragma unroll
        for (int off = 16; off > 0; off >>= 1) {
            float mo = __shfl_xor_sync(0xffffffffu, m, off);
            float so = __shfl_xor_sync(0xffffffffu, s, off);
            float M  = fmaxf(m, mo);
            s = s * __expf(m - M) + so * __expf(mo - M);
            m = M;
        }

        if (lane == 0) {
            const float lse = m + __logf(s);
            const int b    = row / (TM * SP1);
            const int rem  = row % (TM * SP1);
            const int tt   = rem / SP1;
            const int sidx = rem % SP1;

            g_eb[row] = __expf(v[0].x - lse);
            float el = 0.f;
            if (sidx < SM_) {
                const int lab = labels[b * SM_ + sidx];
                el = __expf(__ldg(acts + (size_t)row * V + lab) - lse);
            }
            g_el[row] = el;

            __threadfence();                         // release
            atomicAdd(&g_cnt[b][tt >> 3], 1);
        }
        return;
    }

    // =========================== CONSUMER ROLE ===========================
    if (threadIdx.x >= 32) return;                   // warp 0 only
    const int b = blockIdx.x;
    const int l = threadIdx.x;
    const unsigned FULL = 0xffffffffu;

    const int Tb = input_lengths[b];
    const int Sb = label_lengths[b];

    const float* ebb = g_eb + (size_t)b * TM * SP1;
    const float* elb = g_el + (size_t)b * TM * SP1;

    float x   = (l == 0) ? 1.f : 0.f;    // A[2l]
    float y   = 0.f;                     // A[2l+1]
    float top = 0.f;                     // A[64] (warp-uniform)
    float C   = 0.f;                     // accumulated log scale

    float ebx[8], eby[8], ebt[8], elx[8], em1[8], elt[8];

#define STEP(K)                                                               \
    {                                                                         \
        const float py = __shfl_up_sync(FULL, y, 1);  /* A[2l-1] */           \
        const float ly = __shfl_sync(FULL, y, 31);    /* A[63]   */           \
        const float nx = fmaf(py, em1[K], x * ebx[K]);                        \
        const float ny = fmaf(x,  elx[K], y * eby[K]);                        \
        top = fmaf(ly, elt[K], top * ebt[K]);                                 \
        x = nx;  y = ny;                                                      \
    }

    int t = 0;
    const int nblk = (Tb + 7) >> 3;      // Tb == TM here; handle general Tb

    for (int blk = 0; blk < nblk; blk++) {
        // wait for this 8-step group's 520 rows (producer-released)
        if (l == 0) {
            unsigned ns = 64;
            while (ld_cg(&g_cnt[b][blk]) < GRP_ROWS) {
                __nanosleep(ns);
                if (ns < 2048) ns <<= 1;
            }
        }
        __syncwarp(FULL);
        __threadfence();                 // acquire

        const int nsteps = min(8, Tb - t);
#pragma unroll
        for (int k = 0; k < 8; k++) {
            const int tk = t + ((k < nsteps) ? k : 0);
            const float* bt = ebb + tk * SP1;
            const float* lt = elb + tk * SP1;
            ebx[k] = bt[2 * l];
            eby[k] = bt[2 * l + 1];
            ebt[k] = bt[64];
            elx[k] = lt[2 * l];
            em1[k] = l ? lt[2 * l - 1] : 0.f;
            elt[k] = lt[63];
        }

        if (nsteps == 8) {
            STEP(0); STEP(1); STEP(2); STEP(3);
            STEP(4); STEP(5); STEP(6); STEP(7);
        } else {
            for (int k = 0; k < nsteps; k++) STEP(k);
        }
        t += nsteps;

        // non-deferred renorm (8-step gap keeps values >= ~e^-60 in fp32)
        float M = fmaxf(fmaxf(x, y), top);
#pragma unroll
        for (int off = 16; off > 0; off >>= 1)
            M = fmaxf(M, __shfl_xor_sync(FULL, M, off));
        M = fmaxf(M, 1e-35f);
        const float r = __fdividef(1.0f, M);
        x *= r;  y *= r;  top *= r;
        C += __logf(M);
    }
#undef STEP

    // select A[Sb]:  Sb==64 -> top ; else lane Sb/2, component Sb%2
    float res;
    if (Sb >= 64) res = top;
    else          res = __shfl_sync(FULL, (Sb & 1) ? y : x, Sb >> 1);

    if (l == 0) out[b] = -(C + __logf(res));

    // Drain any groups we did not consume (ensures all producers for this
    // batch are finished), then reset counters for the next graph replay.
    if (l == 0) {
        for (int g = nblk; g < NGRP; g++) {
            unsigned ns = 64;
            while (ld_cg(&g_cnt[b][g]) < GRP_ROWS) {
                __nanosleep(ns);
                if (ns < 2048) ns <<= 1;
            }
        }
    }
    __syncwarp(FULL);
    if (l < NGRP) g_cnt[b][l] = 0;
}

// ---------------------------------------------------------------------------
extern "C" void kernel_launch(void* const* d_in, const int* in_sizes, int n_in,
                              void* d_out, int out_size)
{
    const float* acts   = (const float*)d_in[0];
    const int*   labels = (const int*)d_in[1];
    const int*   ilen   = (const int*)d_in[2];
    const int*   llen   = (const int*)d_in[3];
    float*       out    = (float*)d_out;

    const int producer_ctas = (NROWS + 7) / 8;       // 16640
    const int grid = B + producer_ctas;              // consumers first
    rnnt_fused_kernel<<<grid, 256>>>(acts, labels, ilen, llen, out);
}

// round 9
// speedup vs baseline: 2.1592x; 2.1592x over previous
#include <cuda_runtime.h>
#include <cuda_bf16.h>
#include <cstddef>

// Problem constants (fixed by the reference setup)
constexpr int B   = 16;
constexpr int TM  = 128;
constexpr int SM_ = 64;
constexpr int SP1 = SM_ + 1;           // 65
constexpr int ST  = 66;                // padded stride (even -> float2-aligned)
constexpr int V   = 1024;
constexpr int NROWS = B * TM * SP1;    // 133120 logical rows

// Scratch in EXP space, padded stride-66 layout: idx = b*TM*ST + t*ST + s
__device__ float g_eb[B * TM * ST];
__device__ float g_el[B * TM * ST];

// ---------------------------------------------------------------------------
// Kernel A: per-row logsumexp; writes exp-space blank/label probabilities.
// One warp per row; 8x float4 per lane; HBM-bound (~7.1 TB/s achieved).
// ---------------------------------------------------------------------------
__global__ void __launch_bounds__(256)
lse_kernel(const float* __restrict__ acts, const int* __restrict__ labels)
{
    const int row  = blockIdx.x * 8 + (threadIdx.x >> 5);
    const int lane = threadIdx.x & 31;
    if (row >= NROWS) return;

    const float4* p = reinterpret_cast<const float4*>(acts) + (size_t)row * (V / 4);

    float4 v[8];
#pragma unroll
    for (int j = 0; j < 8; j++) v[j] = p[j * 32 + lane];

    float m = v[0].x;
#pragma unroll
    for (int j = 0; j < 8; j++)
        m = fmaxf(m, fmaxf(fmaxf(v[j].x, v[j].y), fmaxf(v[j].z, v[j].w)));
    float s = 0.f;
#pragma unroll
    for (int j = 0; j < 8; j++)
        s += __expf(v[j].x - m) + __expf(v[j].y - m)
           + __expf(v[j].z - m) + __expf(v[j].w - m);
#pragma unroll
    for (int off = 16; off > 0; off >>= 1) {
        float mo = __shfl_xor_sync(0xffffffffu, m, off);
        float so = __shfl_xor_sync(0xffffffffu, s, off);
        float M  = fmaxf(m, mo);
        s = s * __expf(m - M) + so * __expf(mo - M);
        m = M;
    }

    if (lane == 0) {
        const float lse = m + __logf(s);
        const int b    = row / (TM * SP1);
        const int rem  = row % (TM * SP1);
        const int tt   = rem / SP1;
        const int sidx = rem % SP1;
        const int oidx = b * TM * ST + tt * ST + sidx;

        g_eb[oidx] = __expf(v[0].x - lse);   // exp(blank - lse)

        float el = 0.f;
        if (sidx < SM_) {
            const int lab = labels[b * SM_ + sidx];
            el = __expf(__ldg(acts + (size_t)row * V + lab) - lse);  // L1 hit
        }
        g_el[oidx] = el;
    }
}

// ---------------------------------------------------------------------------
// Kernel B: alpha recursion in probability space. One CTA (ONE WARP) / batch.
// Pair layout: lane l holds x = A[2l], y = A[2l+1]; top = A[64] (uniform).
// All operands double-buffer prefetched from global (L2) into registers —
// nothing but shfl+FMA on the serial chain. Renorm = vote + exact 2^64 scale.
// ---------------------------------------------------------------------------
__global__ void __launch_bounds__(32)
alpha_kernel(const int* __restrict__ input_lengths,
             const int* __restrict__ label_lengths,
             float* __restrict__ out)
{
    const int b = blockIdx.x;
    const int l = threadIdx.x;
    const unsigned FULL = 0xffffffffu;

    const int Tb = input_lengths[b];
    const int Sb = label_lengths[b];

    const float* __restrict__ ebb = g_eb + (size_t)b * TM * ST;
    const float* __restrict__ elb = g_el + (size_t)b * TM * ST;

    float x   = (l == 0) ? 1.f : 0.f;    // A[2l]
    float y   = 0.f;                     // A[2l+1]
    float top = 0.f;                     // A[64] (warp-uniform)
    float C   = 0.f;                     // accumulated log scale

    constexpr float THR   = 0x1p-24f;
    constexpr float SCALE = 0x1p64f;
    constexpr float LN_SC = 44.3614195558364998f;   // 64*ln(2)

#define RENORM()                                                              \
    {                                                                         \
        const float Ml = fmaxf(fmaxf(x, y), top);                             \
        if (__all_sync(FULL, Ml < THR)) {                                     \
            x *= SCALE;  y *= SCALE;  top *= SCALE;  C -= LN_SC;              \
        }                                                                     \
    }

    // ---- fast path: Tb == TM (the benchmark shape) -------------------------
    if (Tb == TM) {
        float2 peb_a[8], pel_a[8];
        float  pem1_a[8], pebt_a[8], pelt_a[8];
        float2 peb_b[8], pel_b[8];
        float  pem1_b[8], pebt_b[8], pelt_b[8];

#define PREFETCH(S, T0)                                                       \
    {                                                                         \
        _Pragma("unroll")                                                     \
        for (int k = 0; k < 8; k++) {                                         \
            peb_##S[k] = __ldg(reinterpret_cast<const float2*>(               \
                                   ebb + ((T0) + k) * ST + 2 * l));           \
            pel_##S[k] = __ldg(reinterpret_cast<const float2*>(               \
                                   elb + ((T0) + k) * ST + 2 * l));           \
        }                                                                     \
        const float ebtv = __ldg(ebb + ((T0) + (l & 7)) * ST + 64);           \
        const float eltv = __ldg(elb + ((T0) + (l & 7)) * ST + 63);           \
        _Pragma("unroll")                                                     \
        for (int k = 0; k < 8; k++) {                                         \
            const float s_ = __shfl_up_sync(FULL, pel_##S[k].y, 1);           \
            pem1_##S[k] = l ? s_ : 0.f;                                       \
            pebt_##S[k] = __shfl_sync(FULL, ebtv, k);                         \
            pelt_##S[k] = __shfl_sync(FULL, eltv, k);                         \
        }                                                                     \
    }

#define STEP(S, K)                                                            \
    {                                                                         \
        const float py = __shfl_up_sync(FULL, y, 1);   /* A[2l-1] */          \
        const float ly = __shfl_sync(FULL, y, 31);     /* A[63]   */          \
        const float nx = fmaf(py, pem1_##S[K], x * peb_##S[K].x);             \
        const float ny = fmaf(x, pel_##S[K].x, y * peb_##S[K].y);             \
        top = fmaf(ly, pelt_##S[K], top * pebt_##S[K]);                       \
        x = nx;  y = ny;                                                      \
    }

#define COMPUTE(S)                                                            \
    {                                                                         \
        STEP(S, 0); STEP(S, 1); STEP(S, 2); STEP(S, 3);                       \
        RENORM();                                                             \
        STEP(S, 4); STEP(S, 5); STEP(S, 6); STEP(S, 7);                       \
        RENORM();                                                             \
    }

        PREFETCH(a, 0);
#pragma unroll
        for (int h = 0; h < 8; h++) {
            const int t0 = 16 * h;
            PREFETCH(b, t0 + 8);
            COMPUTE(a);
            if (h < 7) PREFETCH(a, t0 + 16);
            COMPUTE(b);
        }
#undef COMPUTE
#undef STEP
#undef PREFETCH
    } else {
        // ---- generic slow path (never taken by this benchmark) -------------
        for (int t = 0; t < Tb; t++) {
            const float* bt = ebb + t * ST;
            const float* lt = elb + t * ST;
            const float py = __shfl_up_sync(FULL, y, 1);
            const float ly = __shfl_sync(FULL, y, 31);
            const float e1 = l ? __ldg(lt + 2 * l - 1) : 0.f;
            const float nx = fmaf(py, e1, x * __ldg(bt + 2 * l));
            const float ny = fmaf(x, __ldg(lt + 2 * l), y * __ldg(bt + 2 * l + 1));
            top = fmaf(ly, __ldg(lt + 63), top * __ldg(bt + 64));
            x = nx;  y = ny;
            if ((t & 3) == 3) RENORM();
        }
    }
#undef RENORM

    // select A[Sb]:  Sb==64 -> top ; else lane Sb/2, component Sb%2
    float res;
    if (Sb >= 64) res = top;
    else          res = __shfl_sync(FULL, (Sb & 1) ? y : x, Sb >> 1);

    if (l == 0) out[b] = -(C + __logf(res));
}

// ---------------------------------------------------------------------------
extern "C" void kernel_launch(void* const* d_in, const int* in_sizes, int n_in,
                              void* d_out, int out_size)
{
    const float* acts   = (const float*)d_in[0];
    const int*   labels = (const int*)d_in[1];
    const int*   ilen   = (const int*)d_in[2];
    const int*   llen   = (const int*)d_in[3];
    float*       out    = (float*)d_out;

    const int gridA = (NROWS + 7) / 8;
    lse_kernel<<<gridA, 256>>>(acts, labels);

    alpha_kernel<<<B, 32>>>(ilen, llen, out);
}